// round 3
// baseline (speedup 1.0000x reference)
#include <cuda_runtime.h>

#define LL   128
#define NB   32
#define CC   128
#define MM   128   // dim_mlp
#define OO   128   // out
#define NR   (LL*NB)   // 4096 rows

// Scratch (device globals: no allocation allowed)
__device__ float g_A [NR*MM];        // A[r][m],  r = i*NB+b
__device__ float g_Bt[NB*MM*LL];     // Bt[b][m][j]
__device__ float g_HV[NR*MM];        // relu(x@Vw1+vb1)
__device__ float g_V [NR*OO];        // value[r][c]

// ---------------------------------------------------------------------------
// prep1: A = X@W1_top ; B = X@W1_bot + b1 (stored transposed per-b) ;
//        HV = relu(X@Vw1 + vb1)
// grid 256 blocks x 256 threads, 16 rows per block
// ---------------------------------------------------------------------------
__global__ __launch_bounds__(256) void prep1(
    const float* __restrict__ X,  const float* __restrict__ W1,
    const float* __restrict__ b1, const float* __restrict__ Vw1,
    const float* __restrict__ vb1)
{
    __shared__ float xs[16*128];
    const int r0  = blockIdx.x * 16;
    const int tid = threadIdx.x;

    for (int idx = tid; idx < 16*128/4; idx += 256)
        ((float4*)xs)[idx] = ((const float4*)(X + r0*128))[idx];
    __syncthreads();

    const int rl = tid >> 4;            // row in block 0..15
    const int m0 = (tid & 15) * 8;      // output col group
    const int r  = r0 + rl;

    float a[8], bb[8], hv[8];
    #pragma unroll
    for (int q = 0; q < 8; q++) {
        a[q]  = 0.f;
        bb[q] = b1 [m0 + q];
        hv[q] = vb1[m0 + q];
    }

    for (int c = 0; c < 128; c++) {
        const float xv = xs[rl*128 + c];
        float wt[8], wb[8], wv[8];
        *(float4*)&wt[0] = *(const float4*)(W1  +        c*128 + m0);
        *(float4*)&wt[4] = *(const float4*)(W1  +        c*128 + m0 + 4);
        *(float4*)&wb[0] = *(const float4*)(W1  + (128 + c)*128 + m0);
        *(float4*)&wb[4] = *(const float4*)(W1  + (128 + c)*128 + m0 + 4);
        *(float4*)&wv[0] = *(const float4*)(Vw1 +        c*128 + m0);
        *(float4*)&wv[4] = *(const float4*)(Vw1 +        c*128 + m0 + 4);
        #pragma unroll
        for (int q = 0; q < 8; q++) {
            a [q] += xv * wt[q];
            bb[q] += xv * wb[q];
            hv[q] += xv * wv[q];
        }
    }

    const int j = r >> 5;      // r = i*32+b : key index for B rows
    const int b = r & 31;
    #pragma unroll
    for (int q = 0; q < 8; q++) {
        g_A [r*128 + m0 + q]            = a[q];
        g_Bt[b*(MM*LL) + (m0+q)*LL + j] = bb[q];
        g_HV[r*128 + m0 + q]            = fmaxf(hv[q], 0.f);
    }
}

// ---------------------------------------------------------------------------
// prep2: V = HV @ Vw2 + vb2
// ---------------------------------------------------------------------------
__global__ __launch_bounds__(256) void prep2(
    const float* __restrict__ Vw2, const float* __restrict__ vb2)
{
    __shared__ float xs[16*128];
    const int r0  = blockIdx.x * 16;
    const int tid = threadIdx.x;

    for (int idx = tid; idx < 16*128/4; idx += 256)
        ((float4*)xs)[idx] = ((const float4*)(g_HV + r0*128))[idx];
    __syncthreads();

    const int rl = tid >> 4;
    const int m0 = (tid & 15) * 8;
    const int r  = r0 + rl;

    float v[8];
    #pragma unroll
    for (int q = 0; q < 8; q++) v[q] = vb2[m0 + q];

    for (int c = 0; c < 128; c++) {
        const float xv = xs[rl*128 + c];
        float w[8];
        *(float4*)&w[0] = *(const float4*)(Vw2 + c*128 + m0);
        *(float4*)&w[4] = *(const float4*)(Vw2 + c*128 + m0 + 4);
        #pragma unroll
        for (int q = 0; q < 8; q++) v[q] += xv * w[q];
    }
    #pragma unroll
    for (int q = 0; q < 8; q++) g_V[r*128 + m0 + q] = v[q];
}

// ---------------------------------------------------------------------------
// main: per (b, i-tile of 16):
//   for each i: M = relu(A_i + B_b) @ W2 ; out[i,b,c] = sum_j (M[j,c]+b2[c])*V[j,b,c]
// smem: Bt_b 64K + W2 64K + V_b 64K + A 8K + red 8K = 208 KB
// ---------------------------------------------------------------------------
#define SMEM_BYTES ((16384*3 + 2048 + 2048) * 4)

__global__ __launch_bounds__(256) void mainkern(
    const float* __restrict__ W2, const float* __restrict__ b2,
    float* __restrict__ outp)
{
    extern __shared__ float sm[];
    float* sBt  = sm;                 // [m][j]  16384
    float* sW2  = sm + 16384;         // [m][c]  16384
    float* sV   = sm + 32768;         // [j][c]  16384
    float* sA   = sm + 49152;         // [il][m]  2048
    float* sRed = sm + 51200;         // [tj][c]  2048

    const int b   = blockIdx.y;
    const int i0  = blockIdx.x * 16;
    const int tid = threadIdx.x;

    for (int idx = tid; idx < 4096; idx += 256) {
        ((float4*)sBt)[idx] = ((const float4*)(g_Bt + b*16384))[idx];
        ((float4*)sW2)[idx] = ((const float4*)W2)[idx];
    }
    for (int idx = tid; idx < 4096; idx += 256) {
        const int j  = idx >> 5;
        const int c4 = idx & 31;
        ((float4*)sV)[idx] = ((const float4*)(g_V + (j*NB + b)*128))[c4];
    }
    for (int idx = tid; idx < 512; idx += 256) {
        const int il = idx >> 5;
        const int m4 = idx & 31;
        ((float4*)sA)[idx] = ((const float4*)(g_A + ((i0+il)*NB + b)*128))[m4];
    }
    __syncthreads();

    const int tj = tid >> 4;        // 0..15 : j group
    const int tc = tid & 15;        // 0..15 : c group
    const int j0 = tj * 8;
    const int c0 = tc * 8;

    float b2f[8];
    *(float4*)&b2f[0] = *(const float4*)(b2 + c0);
    *(float4*)&b2f[4] = *(const float4*)(b2 + c0 + 4);

    for (int il = 0; il < 16; il++) {
        float acc[8][8];
        #pragma unroll
        for (int jj = 0; jj < 8; jj++)
            #pragma unroll
            for (int cc = 0; cc < 8; cc++) acc[jj][cc] = 0.f;

        const float* aRow = sA + il*128;

        #pragma unroll 4
        for (int m = 0; m < 128; m++) {
            const float am = aRow[m];
            float h[8], w[8];
            *(float4*)&h[0] = *(const float4*)&sBt[m*128 + j0];
            *(float4*)&h[4] = *(const float4*)&sBt[m*128 + j0 + 4];
            #pragma unroll
            for (int q = 0; q < 8; q++) h[q] = fmaxf(h[q] + am, 0.f);
            *(float4*)&w[0] = *(const float4*)&sW2[m*128 + c0];
            *(float4*)&w[4] = *(const float4*)&sW2[m*128 + c0 + 4];
            #pragma unroll
            for (int jj = 0; jj < 8; jj++)
                #pragma unroll
                for (int cc = 0; cc < 8; cc++)
                    acc[jj][cc] += h[jj] * w[cc];
        }

        // epilogue: value-weighted reduction over this thread's 8 j rows
        float s[8];
        #pragma unroll
        for (int cc = 0; cc < 8; cc++) s[cc] = 0.f;
        #pragma unroll
        for (int jj = 0; jj < 8; jj++) {
            float v[8];
            *(float4*)&v[0] = *(const float4*)&sV[(j0+jj)*128 + c0];
            *(float4*)&v[4] = *(const float4*)&sV[(j0+jj)*128 + c0 + 4];
            #pragma unroll
            for (int cc = 0; cc < 8; cc++)
                s[cc] += (acc[jj][cc] + b2f[cc]) * v[cc];
        }
        *(float4*)&sRed[tj*128 + c0]     = *(float4*)&s[0];
        *(float4*)&sRed[tj*128 + c0 + 4] = *(float4*)&s[4];
        __syncthreads();

        if (tid < 128) {
            float t = 0.f;
            #pragma unroll
            for (int g = 0; g < 16; g++) t += sRed[g*128 + tid];
            outp[((i0 + il)*NB + b)*128 + tid] = t;
        }
        __syncthreads();
    }
}

// ---------------------------------------------------------------------------
extern "C" void kernel_launch(void* const* d_in, const int* in_sizes, int n_in,
                              void* d_out, int out_size)
{
    const float* x   = (const float*)d_in[0];
    const float* aw1 = (const float*)d_in[1];
    const float* ab1 = (const float*)d_in[2];
    const float* aw2 = (const float*)d_in[3];
    const float* ab2 = (const float*)d_in[4];
    const float* vw1 = (const float*)d_in[5];
    const float* vb1 = (const float*)d_in[6];
    const float* vw2 = (const float*)d_in[7];
    const float* vb2 = (const float*)d_in[8];
    float* outp = (float*)d_out;

    cudaFuncSetAttribute(mainkern, cudaFuncAttributeMaxDynamicSharedMemorySize,
                         SMEM_BYTES);

    prep1<<<256, 256>>>(x, aw1, ab1, vw1, vb1);
    prep2<<<256, 256>>>(vw2, vb2);
    mainkern<<<dim3(8, 32), 256, SMEM_BYTES>>>(aw2, ab2, outp);
}

// round 5
// speedup vs baseline: 3.1316x; 3.1316x over previous
#include <cuda_runtime.h>
#include <cstdint>

#define NI 32            // i-tiles per CTA
#define GI 4             // grid.x  (GI*NI = 128 = L)

// ---------------- device scratch (no allocs allowed) ----------------
__device__ float g_A [4096*128];        // A[r][m], r = i*32+b   (x@W1_top)
__device__ float g_Bp[32*128*128];      // [b][j][m]             (x@W1_bot + b1)
__device__ float g_HV[4096*128];        // relu(x@Vw1+vb1)
__device__ float g_Vb[32*128*128];      // [b][j][c]             value
__device__ unsigned int g_W2t[128*128]; // W2^T [c][k], tf32-rounded bits

// ---------------- main-kernel smem layout (floats) ----------------
#define F_SA   0                         // 32*128          = 4096
#define F_SB   4096                      // 128*132         = 16896
#define F_SV   (4096 + 16896)            // 128*132
#define F_SW   (4096 + 2*16896)          // 128*132 (uint bits)
#define F_PART (4096 + 3*16896)          // 4*128           = 512
#define F_B2V  (4096 + 3*16896 + 512)    // 128
#define SMEM_MAIN ((4096 + 3*16896 + 512 + 128) * 4)

// ------------------------- prep GEMM core -------------------------
static __device__ __forceinline__ void gemm_core(
    const float* __restrict__ X, const float* __restrict__ W,
    const float* __restrict__ bias, float* __restrict__ out,
    int relu, int bmode)
{
    extern __shared__ float ps[];
    float* sX = ps;            // 64x128
    float* sW = ps + 8192;     // 128x128
    const int r0  = blockIdx.x * 64;
    const int tid = threadIdx.x;

    for (int i = tid; i < 2048; i += 256)
        ((float4*)sX)[i] = ((const float4*)(X + (size_t)r0*128))[i];
    for (int i = tid; i < 4096; i += 256)
        ((float4*)sW)[i] = ((const float4*)W)[i];
    __syncthreads();

    const int ty = tid >> 4, tx = tid & 15;
    float acc[4][8];
    #pragma unroll
    for (int q = 0; q < 4; q++)
        #pragma unroll
        for (int c = 0; c < 8; c++)
            acc[q][c] = bias ? bias[tx*8 + c] : 0.f;

    const float* x0 = sX + ty*4*128;
    #pragma unroll 2
    for (int k = 0; k < 128; k++){
        float a0 = x0[k], a1 = x0[128+k], a2 = x0[256+k], a3 = x0[384+k];
        float w[8];
        *(float4*)&w[0] = *(const float4*)(sW + k*128 + tx*8);
        *(float4*)&w[4] = *(const float4*)(sW + k*128 + tx*8 + 4);
        #pragma unroll
        for (int c = 0; c < 8; c++){
            acc[0][c] += a0*w[c]; acc[1][c] += a1*w[c];
            acc[2][c] += a2*w[c]; acc[3][c] += a3*w[c];
        }
    }

    #pragma unroll
    for (int q = 0; q < 4; q++){
        const int r = r0 + ty*4 + q;
        float o[8];
        #pragma unroll
        for (int c = 0; c < 8; c++){
            float v = acc[q][c];
            o[c] = relu ? fmaxf(v, 0.f) : v;
        }
        size_t addr = bmode ? ((size_t)(r & 31)*16384 + (size_t)(r >> 5)*128 + tx*8)
                            : ((size_t)r*128 + tx*8);
        *(float4*)(out + addr)     = *(float4*)&o[0];
        *(float4*)(out + addr + 4) = *(float4*)&o[4];
    }
}

__global__ __launch_bounds__(256) void prep1k(
    const float* __restrict__ x,   const float* __restrict__ aw1,
    const float* __restrict__ ab1, const float* __restrict__ vw1,
    const float* __restrict__ vb1)
{
    const int cfg = blockIdx.y;
    if (cfg == 0)      gemm_core(x, aw1,         nullptr, g_A,  0, 0);
    else if (cfg == 1) gemm_core(x, aw1 + 16384, ab1,     g_Bp, 0, 1);
    else               gemm_core(x, vw1,         vb1,     g_HV, 1, 0);
}

__global__ __launch_bounds__(256) void prep2k(
    const float* __restrict__ vw2, const float* __restrict__ vb2)
{
    gemm_core(g_HV, vw2, vb2, g_Vb, 0, 1);
}

// W2 [k][c] -> W2^T [c][k], tf32-rounded
__global__ __launch_bounds__(256) void w2prep(const float* __restrict__ aw2)
{
    const int idx = blockIdx.x*256 + threadIdx.x;   // 0..16383
    const int k = idx >> 7, c = idx & 127;
    uint32_t t;
    asm("cvt.rna.tf32.f32 %0, %1;" : "=r"(t) : "f"(aw2[idx]));
    g_W2t[c*128 + k] = t;
}

// ------------------------- main kernel -------------------------
// grid (GI, 32), 256 thr. Warp w: jq = w&3 (32 j-rows), ch = w>>2 (64 c-cols).
// Per i-tile: H = relu(A_i + B) built in mma-A-fragment regs (tf32),
// D = H @ W2 via mma.sync.m16n8k8.tf32 (fp32 accum, regs),
// out[c] = sum_j D[j,c]*V[j,c] + b2[c]*sum_j V[j,c].
__global__ __launch_bounds__(256) void mainkern(
    const float* __restrict__ b2, float* __restrict__ outp)
{
    extern __shared__ float sm[];
    float*    sA  = sm + F_SA;
    float*    sB  = sm + F_SB;     // [j][m], stride 132
    float*    sV  = sm + F_SV;     // [j][c], stride 132
    uint32_t* sW  = (uint32_t*)(sm + F_SW);  // [c][k], stride 132
    float*    sP  = sm + F_PART;   // [jq][c]
    float*    sBV = sm + F_B2V;

    const int tid  = threadIdx.x;
    const int b    = blockIdx.y;
    const int i0   = blockIdx.x * NI;
    const int wid  = tid >> 5, lane = tid & 31;
    const int g    = lane >> 2, tg = lane & 3;
    const int jq   = wid & 3,  ch = wid >> 2;
    const int j0w  = jq * 32;
    const int c0w  = ch * 64;

    // ---- stage smem ----
    for (int idx = tid; idx < NI*32; idx += 256){
        int t = idx >> 5, m4 = idx & 31;
        ((float4*)sA)[idx] = ((const float4*)g_A)[(size_t)((i0 + t)*32 + b)*32 + m4];
    }
    {
        const float4* srcB = (const float4*)(g_Bp + (size_t)b*16384);
        const float4* srcV = (const float4*)(g_Vb + (size_t)b*16384);
        const uint4*  srcW = (const uint4*)g_W2t;
        for (int idx = tid; idx < 4096; idx += 256){
            int row = idx >> 5, q4 = (idx & 31)*4;
            *(float4*)(sB + row*132 + q4) = srcB[idx];
            *(float4*)(sV + row*132 + q4) = srcV[idx];
            *(uint4*) (sW + row*132 + q4) = srcW[idx];
        }
    }
    __syncthreads();

    // ---- sBV[c] = b2[c] * sum_j V[j][c] ----
    if (tid < 128){
        float s = 0.f;
        #pragma unroll 8
        for (int j = 0; j < 128; j++) s += sV[j*132 + tid];
        sBV[tid] = b2[tid] * s;
    }
    __syncthreads();

    // ---- per-i-tile loop ----
    for (int t = 0; t < NI; t++){
        float d[2][8][4];
        #pragma unroll
        for (int jt = 0; jt < 2; jt++)
            #pragma unroll
            for (int nt = 0; nt < 8; nt++)
                #pragma unroll
                for (int q = 0; q < 4; q++) d[jt][nt][q] = 0.f;

        const float* aRow = sA + t*128;

        #pragma unroll 4
        for (int kt = 0; kt < 16; kt++){
            const int k0 = kt*8;
            const float aA0 = aRow[k0 + tg];
            const float aA1 = aRow[k0 + tg + 4];

            uint32_t afr[2][4];
            #pragma unroll
            for (int jt = 0; jt < 2; jt++){
                const int j = j0w + jt*16 + g;
                const float* bR  = sB + j*132 + k0;
                const float* bR8 = sB + (j+8)*132 + k0;
                float h0 = fmaxf(aA0 + bR [tg],     0.f);
                float h1 = fmaxf(aA0 + bR8[tg],     0.f);
                float h2 = fmaxf(aA1 + bR [tg + 4], 0.f);
                float h3 = fmaxf(aA1 + bR8[tg + 4], 0.f);
                asm("cvt.rna.tf32.f32 %0, %1;" : "=r"(afr[jt][0]) : "f"(h0));
                asm("cvt.rna.tf32.f32 %0, %1;" : "=r"(afr[jt][1]) : "f"(h1));
                asm("cvt.rna.tf32.f32 %0, %1;" : "=r"(afr[jt][2]) : "f"(h2));
                asm("cvt.rna.tf32.f32 %0, %1;" : "=r"(afr[jt][3]) : "f"(h3));
            }

            #pragma unroll
            for (int nt = 0; nt < 8; nt++){
                const int c = c0w + nt*8 + g;
                const uint32_t bf0 = sW[c*132 + k0 + tg];
                const uint32_t bf1 = sW[c*132 + k0 + tg + 4];
                #pragma unroll
                for (int jt = 0; jt < 2; jt++){
                    asm volatile(
                        "mma.sync.aligned.m16n8k8.row.col.f32.tf32.tf32.f32 "
                        "{%0,%1,%2,%3}, {%4,%5,%6,%7}, {%8,%9}, {%0,%1,%2,%3};"
                        : "+f"(d[jt][nt][0]), "+f"(d[jt][nt][1]),
                          "+f"(d[jt][nt][2]), "+f"(d[jt][nt][3])
                        : "r"(afr[jt][0]), "r"(afr[jt][1]),
                          "r"(afr[jt][2]), "r"(afr[jt][3]),
                          "r"(bf0), "r"(bf1));
                }
            }
        }

        // ---- epilogue: value-weighted j reduction ----
        #pragma unroll
        for (int nt = 0; nt < 8; nt++){
            const int c = c0w + nt*8 + 2*tg;
            float p0 = 0.f, p1 = 0.f;
            #pragma unroll
            for (int jt = 0; jt < 2; jt++){
                const int j = j0w + jt*16 + g;
                float2 v0 = *(const float2*)(sV + j*132 + c);
                float2 v8 = *(const float2*)(sV + (j+8)*132 + c);
                p0 += d[jt][nt][0]*v0.x + d[jt][nt][2]*v8.x;
                p1 += d[jt][nt][1]*v0.y + d[jt][nt][3]*v8.y;
            }
            #pragma unroll
            for (int m = 4; m < 32; m <<= 1){
                p0 += __shfl_xor_sync(0xffffffffu, p0, m);
                p1 += __shfl_xor_sync(0xffffffffu, p1, m);
            }
            if (g == 0)
                *(float2*)(sP + jq*128 + c) = make_float2(p0, p1);
        }
        __syncthreads();
        if (tid < 128){
            float r = sP[tid] + sP[128+tid] + sP[256+tid] + sP[384+tid] + sBV[tid];
            outp[(size_t)(i0 + t)*4096 + (size_t)b*128 + tid] = r;
        }
        __syncthreads();
    }
}

// ---------------------------------------------------------------------------
extern "C" void kernel_launch(void* const* d_in, const int* in_sizes, int n_in,
                              void* d_out, int out_size)
{
    const float* x   = (const float*)d_in[0];
    const float* aw1 = (const float*)d_in[1];
    const float* ab1 = (const float*)d_in[2];
    const float* aw2 = (const float*)d_in[3];
    const float* ab2 = (const float*)d_in[4];
    const float* vw1 = (const float*)d_in[5];
    const float* vb1 = (const float*)d_in[6];
    const float* vw2 = (const float*)d_in[7];
    const float* vb2 = (const float*)d_in[8];
    float* outp = (float*)d_out;

    cudaFuncSetAttribute(prep1k,   cudaFuncAttributeMaxDynamicSharedMemorySize, 98304);
    cudaFuncSetAttribute(prep2k,   cudaFuncAttributeMaxDynamicSharedMemorySize, 98304);
    cudaFuncSetAttribute(mainkern, cudaFuncAttributeMaxDynamicSharedMemorySize, SMEM_MAIN);

    prep1k<<<dim3(64, 3), 256, 98304>>>(x, aw1, ab1, vw1, vb1);
    prep2k<<<64, 256, 98304>>>(vw2, vb2);
    w2prep<<<64, 256>>>(aw2);
    mainkern<<<dim3(GI, 32), 256, SMEM_MAIN>>>(ab2, outp);
}

// round 6
// speedup vs baseline: 3.3256x; 1.0620x over previous
#include <cuda_runtime.h>
#include <cstdint>

#define NI 32            // i-tiles per CTA
#define GI 4             // grid.x  (GI*NI = 128 = L)

// ---------------- device scratch (no allocs allowed) ----------------
__device__ float g_A [4096*128];        // A[r][m], r = i*32+b   (x@W1_top)
__device__ float g_Bp[32*128*128];      // [b][j][m]             (x@W1_bot + b1)
__device__ float g_HV[4096*128];        // relu(x@Vw1+vb1)
__device__ float g_Vb[32*128*128];      // [b][j][c]             value
__device__ unsigned int g_W2p[128*68*2]; // W2^T pair layout, tf32 bits

// ---------------- main-kernel smem layout (float offsets) ----------------
#define F_SA   0                   // 32 t * 64 float2  = 4096 floats
#define F_SB   4096                // 128 j * 68 float2 = 17408
#define F_SW   21504               // 128 c * 68 float2 = 17408
#define F_SV   38912               // 128 j * 132       = 16896
#define F_SP   55808               // 2 * 4 * 128       = 1024
#define F_BV   56832               // 128
#define SMEM_MAIN (56960 * 4)      // 227840 B

// ------------------------- prep GEMM core -------------------------
static __device__ __forceinline__ void gemm_core(
    const float* __restrict__ X, const float* __restrict__ W,
    const float* __restrict__ bias, float* __restrict__ out,
    int relu, int bmode)
{
    extern __shared__ float ps[];
    float* sX = ps;            // 64x128
    float* sW = ps + 8192;     // 128x128
    const int r0  = blockIdx.x * 64;
    const int tid = threadIdx.x;

    for (int i = tid; i < 2048; i += 256)
        ((float4*)sX)[i] = ((const float4*)(X + (size_t)r0*128))[i];
    for (int i = tid; i < 4096; i += 256)
        ((float4*)sW)[i] = ((const float4*)W)[i];
    __syncthreads();

    const int ty = tid >> 4, tx = tid & 15;
    float acc[4][8];
    #pragma unroll
    for (int q = 0; q < 4; q++)
        #pragma unroll
        for (int c = 0; c < 8; c++)
            acc[q][c] = bias ? bias[tx*8 + c] : 0.f;

    const float* x0 = sX + ty*4*128;
    #pragma unroll 2
    for (int k = 0; k < 128; k++){
        float a0 = x0[k], a1 = x0[128+k], a2 = x0[256+k], a3 = x0[384+k];
        float w[8];
        *(float4*)&w[0] = *(const float4*)(sW + k*128 + tx*8);
        *(float4*)&w[4] = *(const float4*)(sW + k*128 + tx*8 + 4);
        #pragma unroll
        for (int c = 0; c < 8; c++){
            acc[0][c] += a0*w[c]; acc[1][c] += a1*w[c];
            acc[2][c] += a2*w[c]; acc[3][c] += a3*w[c];
        }
    }

    #pragma unroll
    for (int q = 0; q < 4; q++){
        const int r = r0 + ty*4 + q;
        float o[8];
        #pragma unroll
        for (int c = 0; c < 8; c++){
            float v = acc[q][c];
            o[c] = relu ? fmaxf(v, 0.f) : v;
        }
        size_t addr = bmode ? ((size_t)(r & 31)*16384 + (size_t)(r >> 5)*128 + tx*8)
                            : ((size_t)r*128 + tx*8);
        *(float4*)(out + addr)     = *(float4*)&o[0];
        *(float4*)(out + addr + 4) = *(float4*)&o[4];
    }
}

__global__ __launch_bounds__(256) void prep1k(
    const float* __restrict__ x,   const float* __restrict__ aw1,
    const float* __restrict__ ab1, const float* __restrict__ vw1,
    const float* __restrict__ vb1, const float* __restrict__ aw2)
{
    const int cfg = blockIdx.y;
    if (cfg == 0)      gemm_core(x, aw1,         nullptr, g_A,  0, 0);
    else if (cfg == 1) gemm_core(x, aw1 + 16384, ab1,     g_Bp, 0, 1);
    else if (cfg == 2) gemm_core(x, vw1,         vb1,     g_HV, 1, 0);
    else {
        // W2 [k][c] -> pair layout [c][kt*4+tg] float2, tf32-rounded
        const int idx = blockIdx.x*256 + threadIdx.x;   // 0..16383
        const int k = idx >> 7, c = idx & 127;
        uint32_t t;
        asm("cvt.rna.tf32.f32 %0, %1;" : "=r"(t) : "f"(aw2[idx]));
        const int word = (c*68 + (k >> 3)*4 + (k & 3))*2 + ((k >> 2) & 1);
        g_W2p[word] = t;
    }
}

__global__ __launch_bounds__(256) void prep2k(
    const float* __restrict__ vw2, const float* __restrict__ vb2)
{
    gemm_core(g_HV, vw2, vb2, g_Vb, 0, 1);
}

// ------------------------- main kernel -------------------------
// grid (GI, 32), 256 thr, 8 warps: jq = wid&3 (32 j rows), ch = wid>>2 (64 c cols).
// Two i-tiles per pass share W/B fragment loads.
__global__ __launch_bounds__(256) void mainkern(
    const float* __restrict__ b2, float* __restrict__ outp)
{
    extern __shared__ float sm[];
    float*  sA  = sm + F_SA;                      // pairs, word idx = (t*64+kt*4+tg)*2+h
    float*  sB  = sm + F_SB;                      // pairs, (j*68+kt*4+tg)*2+h
    uint32_t* sW = (uint32_t*)(sm + F_SW);        // pairs (tf32 bits)
    float*  sV  = sm + F_SV;                      // [j][c] stride 132
    float*  sP  = sm + F_SP;                      // [tt][jq][c]
    float*  sBV = sm + F_BV;

    const float2*  sA2 = (const float2*)sA;
    const float2*  sB2 = (const float2*)sB;
    const uint2*   sW2 = (const uint2*)sW;

    const int tid  = threadIdx.x;
    const int b    = blockIdx.y;
    const int i0   = blockIdx.x * NI;
    const int wid  = tid >> 5, lane = tid & 31;
    const int g    = lane >> 2, tg = lane & 3;
    const int jq   = wid & 3,  ch = wid >> 2;
    const int j0w  = jq * 32;
    const int c0w  = ch * 64;

    // ---- stage smem ----
    // A rows -> pair layout
    for (int idx = tid; idx < 1024; idx += 256){
        const int t = idx >> 5, h4 = idx & 31;
        float4 v = ((const float4*)g_A)[(size_t)((i0 + t)*32 + b)*32 + h4];
        const int m = h4*4, kt = m >> 3, h = (m >> 2) & 1;
        const int base = (t*64 + kt*4)*2 + h;
        sA[base] = v.x; sA[base+2] = v.y; sA[base+4] = v.z; sA[base+6] = v.w;
    }
    // B -> pair layout ; V -> scalar stride 132
    {
        const float4* srcB = (const float4*)(g_Bp + (size_t)b*16384);
        const float4* srcV = (const float4*)(g_Vb + (size_t)b*16384);
        for (int idx = tid; idx < 4096; idx += 256){
            const int j = idx >> 5, h4 = idx & 31;
            float4 vb = srcB[idx];
            const int m = h4*4, kt = m >> 3, h = (m >> 2) & 1;
            const int base = (j*68 + kt*4)*2 + h;
            sB[base] = vb.x; sB[base+2] = vb.y; sB[base+4] = vb.z; sB[base+6] = vb.w;
            *(float4*)(sV + j*132 + h4*4) = srcV[idx];
        }
    }
    // W pairs: direct copy
    for (int idx = tid; idx < 4352; idx += 256)
        ((uint4*)sW)[idx] = ((const uint4*)g_W2p)[idx];
    __syncthreads();

    // ---- sBV[c] = b2[c] * sum_j V[j][c] ----
    if (tid < 128){
        float s = 0.f;
        #pragma unroll 8
        for (int j = 0; j < 128; j++) s += sV[j*132 + tid];
        sBV[tid] = b2[tid] * s;
    }
    __syncthreads();

    // ---- main loop: 2 i-tiles per pass ----
    for (int t0 = 0; t0 < NI; t0 += 2){
        float d[2][2][8][4];
        #pragma unroll
        for (int tt = 0; tt < 2; tt++)
            #pragma unroll
            for (int jt = 0; jt < 2; jt++)
                #pragma unroll
                for (int nt = 0; nt < 8; nt++)
                    #pragma unroll
                    for (int q = 0; q < 4; q++) d[tt][jt][nt][q] = 0.f;

        #pragma unroll 4
        for (int kt = 0; kt < 16; kt++){
            // W fragments (shared by both tiles)
            uint2 wf[8];
            #pragma unroll
            for (int nt = 0; nt < 8; nt++)
                wf[nt] = sW2[(c0w + nt*8 + g)*68 + kt*4 + tg];
            // B pairs (shared by both tiles)
            float2 bp[2][2];
            #pragma unroll
            for (int jt = 0; jt < 2; jt++){
                const int j = j0w + jt*16 + g;
                bp[jt][0] = sB2[j*68 + kt*4 + tg];
                bp[jt][1] = sB2[(j+8)*68 + kt*4 + tg];
            }
            #pragma unroll
            for (int tt = 0; tt < 2; tt++){
                const float2 ap = sA2[(t0 + tt)*64 + kt*4 + tg];
                uint32_t afr[2][4];
                #pragma unroll
                for (int jt = 0; jt < 2; jt++){
                    float h0 = fmaxf(ap.x + bp[jt][0].x, 0.f);
                    float h1 = fmaxf(ap.x + bp[jt][1].x, 0.f);
                    float h2 = fmaxf(ap.y + bp[jt][0].y, 0.f);
                    float h3 = fmaxf(ap.y + bp[jt][1].y, 0.f);
                    asm("cvt.rna.tf32.f32 %0, %1;" : "=r"(afr[jt][0]) : "f"(h0));
                    asm("cvt.rna.tf32.f32 %0, %1;" : "=r"(afr[jt][1]) : "f"(h1));
                    asm("cvt.rna.tf32.f32 %0, %1;" : "=r"(afr[jt][2]) : "f"(h2));
                    asm("cvt.rna.tf32.f32 %0, %1;" : "=r"(afr[jt][3]) : "f"(h3));
                }
                #pragma unroll
                for (int nt = 0; nt < 8; nt++)
                    #pragma unroll
                    for (int jt = 0; jt < 2; jt++)
                        asm volatile(
                            "mma.sync.aligned.m16n8k8.row.col.f32.tf32.tf32.f32 "
                            "{%0,%1,%2,%3}, {%4,%5,%6,%7}, {%8,%9}, {%0,%1,%2,%3};"
                            : "+f"(d[tt][jt][nt][0]), "+f"(d[tt][jt][nt][1]),
                              "+f"(d[tt][jt][nt][2]), "+f"(d[tt][jt][nt][3])
                            : "r"(afr[jt][0]), "r"(afr[jt][1]),
                              "r"(afr[jt][2]), "r"(afr[jt][3]),
                              "r"(wf[nt].x), "r"(wf[nt].y));
            }
        }

        // ---- epilogue for both tiles ----
        #pragma unroll
        for (int tt = 0; tt < 2; tt++){
            #pragma unroll
            for (int nt = 0; nt < 8; nt++){
                const int c = c0w + nt*8 + 2*tg;
                float p0 = 0.f, p1 = 0.f;
                #pragma unroll
                for (int jt = 0; jt < 2; jt++){
                    const int j = j0w + jt*16 + g;
                    float2 v0 = *(const float2*)(sV + j*132 + c);
                    float2 v8 = *(const float2*)(sV + (j+8)*132 + c);
                    p0 += d[tt][jt][nt][0]*v0.x + d[tt][jt][nt][2]*v8.x;
                    p1 += d[tt][jt][nt][1]*v0.y + d[tt][jt][nt][3]*v8.y;
                }
                #pragma unroll
                for (int m = 4; m < 32; m <<= 1){
                    p0 += __shfl_xor_sync(0xffffffffu, p0, m);
                    p1 += __shfl_xor_sync(0xffffffffu, p1, m);
                }
                if (g == 0)
                    *(float2*)(sP + tt*512 + jq*128 + c) = make_float2(p0, p1);
            }
        }
        __syncthreads();
        {
            const int tt = tid >> 7, c = tid & 127;
            const float* p = sP + tt*512;
            float r = p[c] + p[128+c] + p[256+c] + p[384+c] + sBV[c];
            outp[(size_t)(i0 + t0 + tt)*4096 + (size_t)b*128 + c] = r;
        }
        __syncthreads();
    }
}

// ---------------------------------------------------------------------------
extern "C" void kernel_launch(void* const* d_in, const int* in_sizes, int n_in,
                              void* d_out, int out_size)
{
    const float* x   = (const float*)d_in[0];
    const float* aw1 = (const float*)d_in[1];
    const float* ab1 = (const float*)d_in[2];
    const float* aw2 = (const float*)d_in[3];
    const float* ab2 = (const float*)d_in[4];
    const float* vw1 = (const float*)d_in[5];
    const float* vb1 = (const float*)d_in[6];
    const float* vw2 = (const float*)d_in[7];
    const float* vb2 = (const float*)d_in[8];
    float* outp = (float*)d_out;

    cudaFuncSetAttribute(prep1k,   cudaFuncAttributeMaxDynamicSharedMemorySize, 98304);
    cudaFuncSetAttribute(prep2k,   cudaFuncAttributeMaxDynamicSharedMemorySize, 98304);
    cudaFuncSetAttribute(mainkern, cudaFuncAttributeMaxDynamicSharedMemorySize, SMEM_MAIN);

    prep1k<<<dim3(64, 4), 256, 98304>>>(x, aw1, ab1, vw1, vb1, aw2);
    prep2k<<<64, 256, 98304>>>(vw2, vb2);
    mainkern<<<dim3(GI, 32), 256, SMEM_MAIN>>>(ab2, outp);
}

// round 10
// speedup vs baseline: 4.8082x; 1.4458x over previous
#include <cuda_runtime.h>
#include <cuda_fp16.h>
#include <cstdint>

#define NI 32            // i-tiles per CTA
#define GI 4             // grid.x (GI*NI = 128 = L)

// ---------------- device scratch (no allocs allowed) ----------------
__device__ unsigned int g_Ah[4096*64];     // A fp16 pairs [r][64], r=i*32+b
__device__ unsigned int g_Bh[32*128*64];   // [b][j][64] fp16 pairs
__device__ float        g_Vb[32*128*128];  // [b][j][c] fp32 value
__device__ uint2        g_W2h[128*32];     // [c][kt*4+tg] fp16 frag pairs

// ---------------- main smem layout (float units) ----------------
#define F_SA 0                 // 32*68 uints
#define F_SB 2176              // 128*68 uints
#define F_SW 10880             // 128*36 uint2 = 9216 floats
#define F_SV 20096             // 128*136 floats
#define F_SP 37504             // 2*4*128
#define F_BV 38528             // 128
#define SMEM_MAIN (38656*4)

static __device__ __forceinline__ uint32_t pack_h2(float lo, float hi){
    uint32_t r;
    asm("cvt.rn.f16x2.f32 %0, %1, %2;" : "=r"(r) : "f"(hi), "f"(lo));
    return r;
}
static __device__ __forceinline__ uint32_t relu2add(uint32_t a, uint32_t b){
    uint32_t r;
    asm("{ .reg .b32 t; add.f16x2 t, %1, %2; max.f16x2 %0, t, %3; }"
        : "=r"(r) : "r"(a), "r"(b), "r"(0u));
    return r;
}

// ------------------------- prep: pipelined 64x128x128 GEMM core ---------
static __device__ __forceinline__ void gemm_inner(
    const float* __restrict__ sXr, const float* __restrict__ sW,
    float acc[4][8], int tx)
{
    float4 w0 = *(const float4*)(sW + tx*8);
    float4 w1 = *(const float4*)(sW + tx*8 + 4);
    float a0 = sXr[0], a1 = sXr[128], a2 = sXr[256], a3 = sXr[384];
    #pragma unroll 2
    for (int k = 0; k < 128; k++){
        float4 nw0, nw1; float n0 = 0.f, n1 = 0.f, n2 = 0.f, n3 = 0.f;
        if (k < 127){
            nw0 = *(const float4*)(sW + (k+1)*128 + tx*8);
            nw1 = *(const float4*)(sW + (k+1)*128 + tx*8 + 4);
            n0 = sXr[k+1]; n1 = sXr[129+k]; n2 = sXr[257+k]; n3 = sXr[385+k];
        } else { nw0 = w0; nw1 = w1; }
        float w[8] = {w0.x,w0.y,w0.z,w0.w,w1.x,w1.y,w1.z,w1.w};
        #pragma unroll
        for (int c = 0; c < 8; c++){
            acc[0][c] += a0*w[c]; acc[1][c] += a1*w[c];
            acc[2][c] += a2*w[c]; acc[3][c] += a3*w[c];
        }
        w0 = nw0; w1 = nw1; a0 = n0; a1 = n1; a2 = n2; a3 = n3;
    }
}

// cfg0: A=x@W1_top -> g_Ah fp16 ; cfg1: B=x@W1_bot+b1 -> g_Bh fp16 ;
// cfg2: V=relu(x@Vw1+vb1)@Vw2+vb2 -> g_Vb fp32 (two layers, one CTA) ;
// cfg3: W2 -> g_W2h fp16 fragment layout (16 CTAs only)
__global__ __launch_bounds__(256) void prep1k(
    const float* __restrict__ x,   const float* __restrict__ aw1,
    const float* __restrict__ ab1, const float* __restrict__ vw1,
    const float* __restrict__ vb1, const float* __restrict__ vw2,
    const float* __restrict__ vb2, const float* __restrict__ aw2)
{
    const int cfg = blockIdx.y;
    const int tid = threadIdx.x;

    if (cfg == 3){
        if (blockIdx.x >= 16) return;
        const int idx = blockIdx.x*256 + tid;      // 0..4095
        const int c = idx >> 5, kt = (idx >> 2) & 7, tg = idx & 3;
        const int k0 = kt*16 + 2*tg;
        uint2 o;
        o.x = pack_h2(aw2[(k0  )*128 + c], aw2[(k0+1)*128 + c]);
        o.y = pack_h2(aw2[(k0+8)*128 + c], aw2[(k0+9)*128 + c]);
        g_W2h[c*32 + kt*4 + tg] = o;
        return;
    }

    extern __shared__ float ps[];
    float* sX = ps;            // 64x128
    float* sW = ps + 8192;     // 128x128
    const int r0 = blockIdx.x * 64;

    const float* Wsrc = (cfg == 0) ? aw1 : (cfg == 1) ? (aw1 + 16384) : vw1;
    for (int i = tid; i < 2048; i += 256)
        ((float4*)sX)[i] = ((const float4*)(x + (size_t)r0*128))[i];
    for (int i = tid; i < 4096; i += 256)
        ((float4*)sW)[i] = ((const float4*)Wsrc)[i];
    __syncthreads();

    const int ty = tid >> 4, tx = tid & 15;
    const float* bias = (cfg == 0) ? nullptr : (cfg == 1) ? ab1 : vb1;

    float acc[4][8];
    #pragma unroll
    for (int q = 0; q < 4; q++)
        #pragma unroll
        for (int c = 0; c < 8; c++)
            acc[q][c] = bias ? bias[tx*8 + c] : 0.f;

    gemm_inner(sX + ty*4*128, sW, acc, tx);

    if (cfg == 0 || cfg == 1){
        #pragma unroll
        for (int q = 0; q < 4; q++){
            const int r = r0 + ty*4 + q;
            uint4 o;
            o.x = pack_h2(acc[q][0], acc[q][1]);
            o.y = pack_h2(acc[q][2], acc[q][3]);
            o.z = pack_h2(acc[q][4], acc[q][5]);
            o.w = pack_h2(acc[q][6], acc[q][7]);
            size_t addr = (cfg == 0) ? ((size_t)r*64 + tx*4)
                        : ((size_t)(r & 31)*8192 + (size_t)(r >> 5)*64 + tx*4);
            *(uint4*)( (cfg == 0 ? g_Ah : g_Bh) + addr ) = o;
        }
        return;
    }

    // cfg2: write relu(layer1) back into sX, stage Vw2, run layer2
    __syncthreads();
    #pragma unroll
    for (int q = 0; q < 4; q++){
        float o[8];
        #pragma unroll
        for (int c = 0; c < 8; c++) o[c] = fmaxf(acc[q][c], 0.f);
        *(float4*)(sX + (ty*4+q)*128 + tx*8)     = *(float4*)&o[0];
        *(float4*)(sX + (ty*4+q)*128 + tx*8 + 4) = *(float4*)&o[4];
    }
    for (int i = tid; i < 4096; i += 256)
        ((float4*)sW)[i] = ((const float4*)vw2)[i];
    __syncthreads();

    float acc2[4][8];
    #pragma unroll
    for (int q = 0; q < 4; q++)
        #pragma unroll
        for (int c = 0; c < 8; c++) acc2[q][c] = vb2[tx*8 + c];
    gemm_inner(sX + ty*4*128, sW, acc2, tx);

    #pragma unroll
    for (int q = 0; q < 4; q++){
        const int r = r0 + ty*4 + q;
        size_t addr = (size_t)(r & 31)*16384 + (size_t)(r >> 5)*128 + tx*8;
        *(float4*)(g_Vb + addr)     = *(float4*)&acc2[q][0];
        *(float4*)(g_Vb + addr + 4) = *(float4*)&acc2[q][4];
    }
}

// ------------------------- main kernel -------------------------
// grid (GI,32), 512 thr, 16 warps: jq=wid&3 (32 j), ch=wid>>2 (32 c).
// 2 i-tiles per pass. H built as fp16x2 fragments, mma m16n8k16.f16.
__global__ __launch_bounds__(512) void mainkern(
    const float* __restrict__ b2, float* __restrict__ outp)
{
    extern __shared__ float sm[];
    uint32_t* sA  = (uint32_t*)(sm + F_SA);   // [t][pair] stride 68
    uint32_t* sB  = (uint32_t*)(sm + F_SB);   // [j][pair] stride 68
    uint2*    sW  = (uint2*)  (sm + F_SW);    // [c][kt*4+tg] stride 36
    float*    sV  = sm + F_SV;                // [j][c] stride 136
    float*    sP  = sm + F_SP;
    float*    sBV = sm + F_BV;

    const int tid  = threadIdx.x;
    const int b    = blockIdx.y;
    const int i0   = blockIdx.x * NI;
    const int wid  = tid >> 5, lane = tid & 31;
    const int g    = lane >> 2, tg = lane & 3;
    const int jq   = wid & 3,  ch = wid >> 2;
    const int j0w  = jq * 32;
    const int c0w  = ch * 32;

    // ---- stage smem ----
    for (int idx = tid; idx < 512; idx += 512){
        int t = idx >> 4, q = idx & 15;
        uint4 v = ((const uint4*)g_Ah)[(size_t)((i0 + t)*32 + b)*16 + q];
        *(uint4*)(sA + t*68 + q*4) = v;
    }
    for (int idx = tid; idx < 2048; idx += 512){
        int j = idx >> 4, q = idx & 15;
        uint4 v = ((const uint4*)g_Bh)[((size_t)b*128 + j)*16 + q];
        *(uint4*)(sB + j*68 + q*4) = v;
    }
    // W2: 128 c x 16 uint4 (= 32 uint2) each  -> 2048 uint4 total
    for (int idx = tid; idx < 2048; idx += 512){
        int c = idx >> 4, q = idx & 15;
        uint4 v = ((const uint4*)g_W2h)[c*16 + q];
        *(uint4*)((uint32_t*)sW + c*72 + q*4) = v;
    }
    for (int idx = tid; idx < 4096; idx += 512){
        int j = idx >> 5, q = idx & 31;
        float4 v = ((const float4*)g_Vb)[((size_t)b*128 + j)*32 + q];
        *(float4*)(sV + j*136 + q*4) = v;
    }
    __syncthreads();

    if (tid < 128){
        float s = 0.f;
        #pragma unroll 8
        for (int j = 0; j < 128; j++) s += sV[j*136 + tid];
        sBV[tid] = b2[tid] * s;
    }
    __syncthreads();

    for (int t0 = 0; t0 < NI; t0 += 2){
        float d[2][2][4][4];
        #pragma unroll
        for (int tt = 0; tt < 2; tt++)
            #pragma unroll
            for (int jt = 0; jt < 2; jt++)
                #pragma unroll
                for (int nt = 0; nt < 4; nt++)
                    #pragma unroll
                    for (int q = 0; q < 4; q++) d[tt][jt][nt][q] = 0.f;

        #pragma unroll
        for (int kt = 0; kt < 8; kt++){
            uint32_t ub[2][2][2];          // [jt][row g/g+8][khalf]
            #pragma unroll
            for (int jt = 0; jt < 2; jt++){
                const int j = j0w + jt*16 + g;
                ub[jt][0][0] = sB[j*68     + kt*8 + tg];
                ub[jt][0][1] = sB[j*68     + kt*8 + 4 + tg];
                ub[jt][1][0] = sB[(j+8)*68 + kt*8 + tg];
                ub[jt][1][1] = sB[(j+8)*68 + kt*8 + 4 + tg];
            }
            uint32_t fr[2][2][4];          // [tt][jt][a0..a3]
            #pragma unroll
            for (int tt = 0; tt < 2; tt++){
                const uint32_t uA0 = sA[(t0+tt)*68 + kt*8 + tg];
                const uint32_t uA1 = sA[(t0+tt)*68 + kt*8 + 4 + tg];
                #pragma unroll
                for (int jt = 0; jt < 2; jt++){
                    fr[tt][jt][0] = relu2add(uA0, ub[jt][0][0]);
                    fr[tt][jt][1] = relu2add(uA0, ub[jt][1][0]);
                    fr[tt][jt][2] = relu2add(uA1, ub[jt][0][1]);
                    fr[tt][jt][3] = relu2add(uA1, ub[jt][1][1]);
                }
            }
            #pragma unroll
            for (int nt = 0; nt < 4; nt++){
                const uint2 wf = sW[(c0w + nt*8 + g)*36 + kt*4 + tg];
                #pragma unroll
                for (int tt = 0; tt < 2; tt++)
                    #pragma unroll
                    for (int jt = 0; jt < 2; jt++)
                        asm volatile(
                            "mma.sync.aligned.m16n8k16.row.col.f32.f16.f16.f32 "
                            "{%0,%1,%2,%3}, {%4,%5,%6,%7}, {%8,%9}, {%0,%1,%2,%3};"
                            : "+f"(d[tt][jt][nt][0]), "+f"(d[tt][jt][nt][1]),
                              "+f"(d[tt][jt][nt][2]), "+f"(d[tt][jt][nt][3])
                            : "r"(fr[tt][jt][0]), "r"(fr[tt][jt][1]),
                              "r"(fr[tt][jt][2]), "r"(fr[tt][jt][3]),
                              "r"(wf.x), "r"(wf.y));
            }
        }

        // ---- epilogue ----
        #pragma unroll
        for (int tt = 0; tt < 2; tt++){
            #pragma unroll
            for (int nt = 0; nt < 4; nt++){
                const int c = c0w + nt*8 + 2*tg;
                float p0 = 0.f, p1 = 0.f;
                #pragma unroll
                for (int jt = 0; jt < 2; jt++){
                    const int j = j0w + jt*16 + g;
                    float2 v0 = *(const float2*)(sV + j*136 + c);
                    float2 v8 = *(const float2*)(sV + (j+8)*136 + c);
                    p0 += d[tt][jt][nt][0]*v0.x + d[tt][jt][nt][2]*v8.x;
                    p1 += d[tt][jt][nt][1]*v0.y + d[tt][jt][nt][3]*v8.y;
                }
                #pragma unroll
                for (int m = 4; m < 32; m <<= 1){
                    p0 += __shfl_xor_sync(0xffffffffu, p0, m);
                    p1 += __shfl_xor_sync(0xffffffffu, p1, m);
                }
                if (g == 0)
                    *(float2*)(sP + tt*512 + jq*128 + c) = make_float2(p0, p1);
            }
        }
        __syncthreads();
        if (tid < 256){
            const int tt = tid >> 7, c = tid & 127;
            const float* p = sP + tt*512;
            float r = p[c] + p[128+c] + p[256+c] + p[384+c] + sBV[c];
            outp[(size_t)(i0 + t0 + tt)*4096 + (size_t)b*128 + c] = r;
        }
        __syncthreads();
    }
}

// ---------------------------------------------------------------------------
extern "C" void kernel_launch(void* const* d_in, const int* in_sizes, int n_in,
                              void* d_out, int out_size)
{
    const float* x   = (const float*)d_in[0];
    const float* aw1 = (const float*)d_in[1];
    const float* ab1 = (const float*)d_in[2];
    const float* aw2 = (const float*)d_in[3];
    const float* ab2 = (const float*)d_in[4];
    const float* vw1 = (const float*)d_in[5];
    const float* vb1 = (const float*)d_in[6];
    const float* vw2 = (const float*)d_in[7];
    const float* vb2 = (const float*)d_in[8];
    float* outp = (float*)d_out;

    cudaFuncSetAttribute(prep1k,   cudaFuncAttributeMaxDynamicSharedMemorySize, 98304);
    cudaFuncSetAttribute(mainkern, cudaFuncAttributeMaxDynamicSharedMemorySize, SMEM_MAIN);

    prep1k<<<dim3(64, 4), 256, 98304>>>(x, aw1, ab1, vw1, vb1, vw2, vb2, aw2);
    mainkern<<<dim3(GI, 32), 512, SMEM_MAIN>>>(ab2, outp);
}